// round 1
// baseline (speedup 1.0000x reference)
#include <cuda_runtime.h>

#define BATCH 2048
#define TT    512
#define HID   64
#define GATES 256   // 4*HID
#define NB    8     // batch rows per CTA
#define NTHR  256

__device__ __forceinline__ float fast_sigmoid(float v) {
    // stable: v<<0 -> expf(-v)=inf -> 0 ; v>>0 -> expf->0 -> 1
    return 1.0f / (1.0f + __expf(-v));
}

__device__ __forceinline__ float fast_tanh(float v) {
    // stable form: tanh(|v|) = (1-e)/(1+e), e = exp(-2|v|) in (0,1]
    float av = fabsf(v);
    float e  = __expf(-2.0f * av);
    float th = (1.0f - e) / (1.0f + e);
    return copysignf(th, v);
}

__global__ __launch_bounds__(NTHR, 2)
void lstm_kernel(const float* __restrict__ x,
                 const float* __restrict__ W_ih,
                 const float* __restrict__ W_hh,
                 const float* __restrict__ b_ih,
                 const float* __restrict__ b_hh,
                 const float* __restrict__ W_d,
                 const float* __restrict__ b_d,
                 float* __restrict__ out) {
    __shared__ float x_s[NB][TT];      // 16 KB: this CTA's input slab
    __shared__ float h_s[NB][HID];     // 2 KB : hidden state
    __shared__ float g_s[NB][GATES];   // 8 KB : activated gates (i,f,g,o)

    const int tid  = threadIdx.x;      // = gate column j in [0,256)
    const int row0 = blockIdx.x * NB;

    // --- per-thread weights for gate column j, kept in registers ---
    float w[HID];
#pragma unroll
    for (int k = 0; k < HID; k++) w[k] = W_hh[tid * HID + k];
    const float wih  = W_ih[tid];                  // W_ih[:,0]
    const float bias = b_ih[tid] + b_hh[tid];
    const int gtype  = tid >> 6;                   // 0:i 1:f 2:g 3:o (warp-uniform)

    // --- stage x slab into SMEM (coalesced) ---
    for (int i = tid; i < NB * TT; i += NTHR) {
        int r = i >> 9;          // /512
        int t = i & (TT - 1);
        x_s[r][t] = x[(row0 + r) * TT + t];
    }
    // --- init h = 0 ---
    for (int i = tid; i < NB * HID; i += NTHR)
        ((float*)h_s)[i] = 0.0f;

    // --- phase-2 ownership: thread handles pairs (tid) and (tid+256) of NB*HID=512 ---
    float c0 = 0.0f, c1 = 0.0f;
    const int r0a = (tid)        >> 6, m0 = (tid)        & 63;
    const int r1a = (tid + NTHR) >> 6, m1 = (tid + NTHR) & 63;

    __syncthreads();

    for (int t = 0; t < TT; t++) {
        // ---------- phase 1: gate pre-activations + activation ----------
        float acc[NB];
#pragma unroll
        for (int r = 0; r < NB; r++)
            acc[r] = fmaf(x_s[r][t], wih, bias);

#pragma unroll
        for (int k4 = 0; k4 < HID; k4 += 4) {
#pragma unroll
            for (int r = 0; r < NB; r++) {
                float4 h4 = *(const float4*)&h_s[r][k4];   // broadcast LDS.128
                acc[r] = fmaf(w[k4 + 0], h4.x, acc[r]);
                acc[r] = fmaf(w[k4 + 1], h4.y, acc[r]);
                acc[r] = fmaf(w[k4 + 2], h4.z, acc[r]);
                acc[r] = fmaf(w[k4 + 3], h4.w, acc[r]);
            }
        }

        if (gtype == 2) {       // g gate: tanh   (warp-uniform branch)
#pragma unroll
            for (int r = 0; r < NB; r++) g_s[r][tid] = fast_tanh(acc[r]);
        } else {                // i, f, o gates: sigmoid
#pragma unroll
            for (int r = 0; r < NB; r++) g_s[r][tid] = fast_sigmoid(acc[r]);
        }
        __syncthreads();

        // ---------- phase 2: cell/hidden update ----------
        {
            float i_ = g_s[r0a][m0];
            float f_ = g_s[r0a][64 + m0];
            float gg = g_s[r0a][128 + m0];
            float o_ = g_s[r0a][192 + m0];
            c0 = fmaf(f_, c0, i_ * gg);
            h_s[r0a][m0] = o_ * fast_tanh(c0);
        }
        {
            float i_ = g_s[r1a][m1];
            float f_ = g_s[r1a][64 + m1];
            float gg = g_s[r1a][128 + m1];
            float o_ = g_s[r1a][192 + m1];
            c1 = fmaf(f_, c1, i_ * gg);
            h_s[r1a][m1] = o_ * fast_tanh(c1);
        }
        __syncthreads();
    }

    // ---------- final projection: out[r] = h_T . W_d + b_d ----------
    if (tid < NB) {
        float s = b_d[0];
#pragma unroll
        for (int m = 0; m < HID; m++)
            s = fmaf(h_s[tid][m], W_d[m], s);
        out[row0 + tid] = s;
    }
}

extern "C" void kernel_launch(void* const* d_in, const int* in_sizes, int n_in,
                              void* d_out, int out_size) {
    const float* x    = (const float*)d_in[0];
    const float* W_ih = (const float*)d_in[1];
    const float* W_hh = (const float*)d_in[2];
    const float* b_ih = (const float*)d_in[3];
    const float* b_hh = (const float*)d_in[4];
    const float* W_d  = (const float*)d_in[5];
    const float* b_d  = (const float*)d_in[6];
    float* out = (float*)d_out;

    lstm_kernel<<<BATCH / NB, NTHR>>>(x, W_ih, W_hh, b_ih, b_hh, W_d, b_d, out);
}

// round 2
// speedup vs baseline: 1.0586x; 1.0586x over previous
#include <cuda_runtime.h>
#include <string.h>

#define BATCH 2048
#define TT    512
#define HID   64
#define GATES 256   // 4*HID
#define NB    8     // batch rows per CTA
#define NTHR  256

typedef unsigned long long u64;

__device__ __forceinline__ u64 ffma2(u64 a, u64 b, u64 c) {
    u64 d;
    asm("fma.rn.f32x2 %0, %1, %2, %3;" : "=l"(d) : "l"(a), "l"(b), "l"(c));
    return d;
}

__device__ __forceinline__ u64 pack2(float lo, float hi) {
    u64 r;
    asm("mov.b64 %0, {%1, %2};" : "=l"(r) : "f"(lo), "f"(hi));
    return r;
}

__device__ __forceinline__ float sum2(u64 v) {
    float lo, hi;
    asm("mov.b64 {%0, %1}, %2;" : "=f"(lo), "=f"(hi) : "l"(v));
    return lo + hi;
}

__device__ __forceinline__ float fast_sigmoid(float v) {
    return 1.0f / (1.0f + __expf(-v));
}

__device__ __forceinline__ float fast_tanh(float v) {
    float av = fabsf(v);
    float e  = __expf(-2.0f * av);
    float th = (1.0f - e) / (1.0f + e);
    return copysignf(th, v);
}

__global__ __launch_bounds__(NTHR, 2)
void lstm_kernel(const float* __restrict__ x,
                 const float* __restrict__ W_ih,
                 const float* __restrict__ W_hh,
                 const float* __restrict__ b_ih,
                 const float* __restrict__ b_hh,
                 const float* __restrict__ W_d,
                 const float* __restrict__ b_d,
                 float* __restrict__ out) {
    __shared__ float x_s[NB][TT];      // 16 KB: this CTA's input slab
    __shared__ float h_s[NB][HID];     // 2 KB : hidden state (k-contiguous rows)
    __shared__ float g_s[NB][GATES];   // 8 KB : activated gates (i,f,g,o)

    const int tid  = threadIdx.x;      // = gate column j in [0,256)
    const int row0 = blockIdx.x * NB;

    // --- per-thread W_hh row for gate column j, kept packed as 32 x f32x2 ---
    u64 w2[HID / 2];
    {
        const ulonglong2* wp = reinterpret_cast<const ulonglong2*>(W_hh + tid * HID);
#pragma unroll
        for (int q = 0; q < HID / 4; q++) {       // 16 x 16B loads
            ulonglong2 v = wp[q];
            w2[2 * q + 0] = v.x;
            w2[2 * q + 1] = v.y;
        }
    }
    const float wih  = W_ih[tid];                  // W_ih[:,0]
    const float bias = b_ih[tid] + b_hh[tid];
    const int gtype  = tid >> 6;                   // 0:i 1:f 2:g 3:o (warp-uniform)

    // --- stage x slab into SMEM (coalesced) ---
    for (int i = tid; i < NB * TT; i += NTHR) {
        int r = i >> 9;          // /512
        int t = i & (TT - 1);
        x_s[r][t] = x[(row0 + r) * TT + t];
    }
    // --- init h = 0 ---
    for (int i = tid; i < NB * HID; i += NTHR)
        ((float*)h_s)[i] = 0.0f;

    // --- phase-2 ownership: thread handles pairs (tid) and (tid+256) of NB*HID=512 ---
    float c0 = 0.0f, c1 = 0.0f;
    const int r0a = (tid)        >> 6, m0 = (tid)        & 63;
    const int r1a = (tid + NTHR) >> 6, m1 = (tid + NTHR) & 63;

    __syncthreads();

    for (int t = 0; t < TT; t++) {
        // ---------- phase 1: gate pre-activations via packed dual accumulators ----
        // acc[r] = (even-k partial, odd-k partial); init carries x*wih+bias in lo half
        u64 acc[NB];
#pragma unroll
        for (int r = 0; r < NB; r++)
            acc[r] = pack2(fmaf(x_s[r][t], wih, bias), 0.0f);

#pragma unroll
        for (int k4 = 0; k4 < HID; k4 += 4) {
#pragma unroll
            for (int r = 0; r < NB; r++) {
                // one LDS.128 (broadcast) -> two f32x2 h pairs
                ulonglong2 h4 = *reinterpret_cast<const ulonglong2*>(&h_s[r][k4]);
                acc[r] = ffma2(w2[(k4 >> 1) + 0], h4.x, acc[r]);
                acc[r] = ffma2(w2[(k4 >> 1) + 1], h4.y, acc[r]);
            }
        }

        if (gtype == 2) {       // g gate: tanh   (warp-uniform branch)
#pragma unroll
            for (int r = 0; r < NB; r++) g_s[r][tid] = fast_tanh(sum2(acc[r]));
        } else {                // i, f, o gates: sigmoid
#pragma unroll
            for (int r = 0; r < NB; r++) g_s[r][tid] = fast_sigmoid(sum2(acc[r]));
        }
        __syncthreads();

        // ---------- phase 2: cell/hidden update ----------
        {
            float i_ = g_s[r0a][m0];
            float f_ = g_s[r0a][64 + m0];
            float gg = g_s[r0a][128 + m0];
            float o_ = g_s[r0a][192 + m0];
            c0 = fmaf(f_, c0, i_ * gg);
            h_s[r0a][m0] = o_ * fast_tanh(c0);
        }
        {
            float i_ = g_s[r1a][m1];
            float f_ = g_s[r1a][64 + m1];
            float gg = g_s[r1a][128 + m1];
            float o_ = g_s[r1a][192 + m1];
            c1 = fmaf(f_, c1, i_ * gg);
            h_s[r1a][m1] = o_ * fast_tanh(c1);
        }
        __syncthreads();
    }

    // ---------- final projection: out[r] = h_T . W_d + b_d ----------
    if (tid < NB) {
        float s = b_d[0];
#pragma unroll
        for (int m = 0; m < HID; m++)
            s = fmaf(h_s[tid][m], W_d[m], s);
        out[row0 + tid] = s;
    }
}

extern "C" void kernel_launch(void* const* d_in, const int* in_sizes, int n_in,
                              void* d_out, int out_size) {
    const float* x    = (const float*)d_in[0];
    const float* W_ih = (const float*)d_in[1];
    const float* W_hh = (const float*)d_in[2];
    const float* b_ih = (const float*)d_in[3];
    const float* b_hh = (const float*)d_in[4];
    const float* W_d  = (const float*)d_in[5];
    const float* b_d  = (const float*)d_in[6];
    float* out = (float*)d_out;

    lstm_kernel<<<BATCH / NB, NTHR>>>(x, W_ih, W_hh, b_ih, b_hh, W_d, b_d, out);
}